// round 9
// baseline (speedup 1.0000x reference)
#include <cuda_runtime.h>
#include <cuda_bf16.h>
#include <cstdint>

// Image is 2048 x 2048 float32.
#define IMG_H 2048
#define IMG_W 2048
#define NW 32            // u64 words per row (2048 bits)
#define BANDS 32
#define WARM 16
#define PFD 6            // prefetch ring depth in k3

typedef unsigned long long u64;

__device__ u64 d_S [IMG_H * NW];   // original strong bits (x > high)
__device__ u64 d_W [IMG_H * NW];   // weak & interior-column bits
__device__ u64 d_Wf[IMG_H * NW];   // full weak bits (low<=x<=high), no column mask
__device__ u64 d_A0[IMG_H * NW];   // precomputed a-generate: S | (W & staticbase)
__device__ u64 d_So[IMG_H * NW];   // new strong bits after hysteresis (rows 1..2046)
__device__ u64 d_bnd [BANDS * NW]; // speculative outgoing boundary of band k
__device__ u64 d_spec[BANDS * NW]; // speculative incoming boundary of band k
__device__ unsigned d_maxbits;

// ---------------- K0: reset ----------------
__global__ void k0_reset() { d_maxbits = 0u; }

// ---------------- K1: max reduction ----------------
__global__ void k1_max(const float* __restrict__ img) {
    const float4* p4 = reinterpret_cast<const float4*>(img);
    const int n4 = (IMG_H * IMG_W) / 4;
    float m = 0.0f;
    for (int i = blockIdx.x * blockDim.x + threadIdx.x; i < n4;
         i += gridDim.x * blockDim.x) {
        float4 v = p4[i];
        m = fmaxf(m, fmaxf(fmaxf(v.x, v.y), fmaxf(v.z, v.w)));
    }
    for (int o = 16; o > 0; o >>= 1)
        m = fmaxf(m, __shfl_xor_sync(0xffffffffu, m, o));
    __shared__ float sm[32];
    int lane = threadIdx.x & 31, wid = threadIdx.x >> 5;
    if (lane == 0) sm[wid] = m;
    __syncthreads();
    if (wid == 0) {
        int nwarp = blockDim.x >> 5;
        m = (lane < nwarp) ? sm[lane] : 0.0f;
        for (int o = 16; o > 0; o >>= 1)
            m = fmaxf(m, __shfl_xor_sync(0xffffffffu, m, o));
        if (lane == 0)
            atomicMax(reinterpret_cast<int*>(&d_maxbits), __float_as_int(m));
    }
}

// ---------------- K2: pack strong/weak bitmasks (1 warp per row) ----------------
__global__ void k2_pack(const float* __restrict__ img) {
    int gw = (blockIdx.x * blockDim.x + threadIdx.x) >> 5;  // global warp = row
    int lane = threadIdx.x & 31;
    if (gw >= IMG_H) return;
    float mx = __int_as_float((int)d_maxbits);
    float high = mx * 0.15f;
    float low = high * 0.05f;

    const float4* rp = reinterpret_cast<const float4*>(img + (size_t)gw * IMG_W) + lane * 16;
    u64 sb = 0, wb = 0;
#pragma unroll
    for (int k = 0; k < 16; ++k) {
        float4 v = rp[k];
        int b = k * 4;
        sb |= ((u64)(v.x > high)) << (b + 0);
        sb |= ((u64)(v.y > high)) << (b + 1);
        sb |= ((u64)(v.z > high)) << (b + 2);
        sb |= ((u64)(v.w > high)) << (b + 3);
        wb |= ((u64)((v.x >= low) && (v.x <= high))) << (b + 0);
        wb |= ((u64)((v.y >= low) && (v.y <= high))) << (b + 1);
        wb |= ((u64)((v.z >= low) && (v.z <= high))) << (b + 2);
        wb |= ((u64)((v.w >= low) && (v.w <= high))) << (b + 3);
    }
    d_S [gw * NW + lane] = sb;
    d_Wf[gw * NW + lane] = wb;
    if (lane == 0)  wb &= ~1ull;              // column 0 not interior
    if (lane == 31) wb &= ~(1ull << 63);      // column W-1 not interior
    d_W[gw * NW + lane] = wb;
}

// ---------------- K2b: precompute A0 = S | (W & static_base), rows 1..2046 ----------------
__global__ void k2b_pre() {
    const unsigned F = 0xffffffffu;
    int gw = (blockIdx.x * blockDim.x + threadIdx.x) >> 5;
    int l = threadIdx.x & 31;
    int i = gw + 1;
    if (i > IMG_H - 2) return;

    u64 cs = d_S[i * NW + l];
    u64 ns = d_S[(i + 1) * NW + l];
    u64 w  = d_W[i * NW + l];

    u64 csR = __shfl_down_sync(F, cs, 1); if (l == 31) csR = 0;
    u64 nsL = __shfl_up_sync(F, ns, 1);   if (l == 0)  nsL = 0;
    u64 nsR = __shfl_down_sync(F, ns, 1); if (l == 31) nsR = 0;
    u64 SB = ((cs >> 1) | (csR << 63)) | ((ns << 1) | (nsL >> 63)) | ns |
             ((ns >> 1) | (nsR << 63));
    d_A0[i * NW + l] = cs | (w & SB);
}

// ---------------- hysteresis core ----------------
__device__ __forceinline__ u64 dil(u64 s, int l) {
    const unsigned F = 0xffffffffu;
    u64 sl = __shfl_up_sync(F, s, 1);   if (l == 0)  sl = 0;
    u64 sr = __shfl_down_sync(F, s, 1); if (l == 31) sr = 0;
    return s | ((s << 1) | (sl >> 63)) | ((s >> 1) | (sr << 63));
}

// Process rows [ws, re); store d_So for rows in [rs, re); capture s at row rs-1
// into *specp (if non-null). Returns s of row re-1. nb = dilate of incoming state.
// Loop body uses precomputed d_A0:  a = A0 | (w & nb).
__device__ __forceinline__ u64 run_rows(int ws, int rs, int re, u64 nb, int l,
                                        u64* specp) {
    const unsigned F = 0xffffffffu;
    u64 A0r[PFD], Wr[PFD];
#pragma unroll
    for (int d = 0; d < PFD; ++d) {
        int r = ws + d; if (r > IMG_H - 2) r = IMG_H - 2;
        A0r[d] = d_A0[r * NW + l];
        Wr[d]  = d_W [r * NW + l];
    }

    u64 last = 0;
    int i = ws;
#pragma unroll 1
    while (i < re) {
#pragma unroll
        for (int d = 0; d < PFD; ++d) {
            if (i >= re) break;
            u64 a0 = A0r[d];
            u64 w  = Wr[d];
            // prefetch row i+PFD into this slot (clamped)
            int pr = i + PFD; if (pr > IMG_H - 2) pr = IMG_H - 2;
            A0r[d] = d_A0[pr * NW + l];
            Wr[d]  = d_W [pr * NW + l];

            u64 a = a0 | (w & nb);
            u64 p = w & ~a;
            u64 x = a | w;

            // early shuffle of (a0,p0) for right-neighbor boundary bit
            unsigned lo = (unsigned)(a & 1ull) | (((unsigned)(p & 1ull)) << 1);
            unsigned loR = __shfl_down_sync(F, lo, 1);
            if (l == 31) loR = 0;

            u64 t1 = x + a;               // in-word carry chain, cin=0
            bool G = (t1 < x);            // word generate
            bool P = (p == ~0ull);        // word full-propagate
            unsigned Gm = __ballot_sync(F, G);
            unsigned Pm = __ballot_sync(F, P);

            // 32-bit cross-lane carry via adder trick
            unsigned x32 = Gm | Pm;
            unsigned cv32 = (x32 + Gm) ^ (x32 ^ Gm);  // bit l = carry into lane l
            u64 cin = (u64)((cv32 >> l) & 1u);

            u64 t2 = t1 + cin;
            u64 cv = t2 ^ x ^ a;                      // bit j = carry into bit j
            u64 co = (u64)G | (cin & (u64)(t1 == ~0ull));
            u64 s = (cv >> 1) | (co << 63);           // new-strong bits of this row

            if (i >= rs) d_So[i * NW + l] = s;
            else if (specp && i == rs - 1) *specp = s;
            last = s;

            // dilate(s) for next row without extra shuffles
            unsigned cinR = ((cv32 >> l) >> 1) & 1u;
            u64 rb = (u64)((loR & 1u) | ((loR >> 1) & cinR));
            nb = s | ((s << 1) | cin) | ((s >> 1) | (rb << 63));
            ++i;
        }
    }
    return last;
}

// ---------------- K3a: band-parallel speculative hysteresis (no sync) ----------------
__global__ void __launch_bounds__(32, 1) k3a_spec() {
    const int l = threadIdx.x;
    const int k = blockIdx.x;
    const int rs = 1 + (2046 * k) / BANDS;
    const int re = 1 + (2046 * (k + 1)) / BANDS;

    if (k == 0) {
        u64 s0 = d_S[0 * NW + l];
        u64 last = run_rows(rs, rs, re, dil(s0, l), l, nullptr);
        d_bnd[0 * NW + l] = last;
    } else {
        int ws = rs - WARM;
        u64 seed = d_S[(ws - 1) * NW + l];
        u64 spec = 0;
        u64 last = run_rows(ws, rs, re, dil(seed, l), l, &spec);
        d_spec[k * NW + l] = spec;
        d_bnd[k * NW + l] = last;
    }
}

// ---------------- K3b: verify; sequential in-block fixup if needed ----------------
__global__ void __launch_bounds__(BANDS * 32, 1) k3b_fix() {
    const unsigned F = 0xffffffffu;
    __shared__ u64 tout[BANDS * 32];
    __shared__ int wmatch[BANDS];
    __shared__ int allm;
    const int l = threadIdx.x & 31;
    const int k = threadIdx.x >> 5;   // band handled by this warp

    int m = 1;
    if (k > 0) {
        u64 spec = d_spec[k * NW + l];
        u64 po = d_bnd[(k - 1) * NW + l];
        m = (__ballot_sync(F, spec == po) == F) ? 1 : 0;
    }
    if (l == 0) wmatch[k] = m;
    __syncthreads();
    if (threadIdx.x == 0) {
        int a = 1;
#pragma unroll
        for (int i = 0; i < BANDS; ++i) a &= wmatch[i];
        allm = a;
    }
    __syncthreads();
    if (allm) return;   // expected case: all speculation verified exact

    // Sequential fixup with cheap smem hand-off. Exactness: if the true
    // incoming boundary equals the speculated one, the band's d_So rows and
    // outgoing boundary are already correct; otherwise recompute from truth.
    for (int step = 0; step < BANDS; ++step) {
        if (k == step) {
            if (k == 0) {
                tout[0 * 32 + l] = d_bnd[0 * NW + l];
            } else {
                const int rs = 1 + (2046 * k) / BANDS;
                const int re = 1 + (2046 * (k + 1)) / BANDS;
                u64 tin = tout[(k - 1) * 32 + l];
                u64 spec = d_spec[k * NW + l];
                if (__ballot_sync(F, tin == spec) == F) {
                    tout[k * 32 + l] = d_bnd[k * NW + l];
                } else {
                    u64 last = run_rows(rs, rs, re, dil(tin, l), l, nullptr);
                    tout[k * 32 + l] = last;
                }
            }
        }
        __syncthreads();
    }
}

// ---------------- K4: reconstruct float output from bitmasks only ----------------
__global__ void k4_out(float* __restrict__ out) {
    int idx = blockIdx.x * blockDim.x + threadIdx.x;   // one float4 per thread
    const int n4 = (IMG_H * IMG_W) / 4;
    if (idx >= n4) return;
    int row = idx >> 9;          // 512 float4 per row
    int c = (idx & 511) * 4;
    int wi = row * NW + (c >> 6);
    int sh = c & 63;

    u64 sb = d_S [wi] >> sh;
    u64 fb = d_Wf[wi] >> sh;

    float4 o;
    if (row == 0 || row == IMG_H - 1) {
#pragma unroll
        for (int j = 0; j < 4; ++j) {
            float t = ((sb >> j) & 1ull) ? 255.0f : (((fb >> j) & 1ull) ? 25.0f : 0.0f);
            (&o.x)[j] = t;
        }
    } else {
        u64 wb = d_W [wi] >> sh;
        u64 ob = d_So[wi] >> sh;
#pragma unroll
        for (int j = 0; j < 4; ++j) {
            float r;
            if ((wb >> j) & 1ull)      r = ((ob >> j) & 1ull) ? 255.0f : 0.0f;
            else if ((sb >> j) & 1ull) r = 255.0f;
            else                       r = ((fb >> j) & 1ull) ? 25.0f : 0.0f;
            (&o.x)[j] = r;
        }
    }
    reinterpret_cast<float4*>(out)[idx] = o;
}

extern "C" void kernel_launch(void* const* d_in, const int* in_sizes, int n_in,
                              void* d_out, int out_size) {
    const float* img = (const float*)d_in[0];
    float* out = (float*)d_out;
    (void)in_sizes; (void)n_in; (void)out_size;

    k0_reset<<<1, 1>>>();
    k1_max<<<256, 256>>>(img);
    k2_pack<<<IMG_H / 8, 256>>>(img);          // 1 warp per row
    k2b_pre<<<(IMG_H + 7) / 8, 256>>>();       // 1 warp per interior row
    k3a_spec<<<BANDS, 32>>>();
    k3b_fix<<<1, BANDS * 32>>>();
    k4_out<<<(IMG_H * IMG_W / 4 + 255) / 256, 256>>>(out);
}

// round 11
// speedup vs baseline: 1.7573x; 1.7573x over previous
#include <cuda_runtime.h>
#include <cuda_bf16.h>
#include <cstdint>

// Image is 2048 x 2048 float32.
#define IMG_H 2048
#define IMG_W 2048
#define NW 32            // u64 words per row (2048 bits)
#define BANDS 128        // 16 owned rows per band
#define OWN 16
#define WARM 10
#define PFD 4            // prefetch ring depth

typedef unsigned long long u64;

__device__ u64 d_S [IMG_H * NW];   // original strong bits (x > high)
__device__ u64 d_W [IMG_H * NW];   // weak & interior-column bits
__device__ u64 d_Wf[IMG_H * NW];   // full weak bits (low<=x<=high)
__device__ u64 d_A0[IMG_H * NW];   // precomputed a-generate: S | (W & staticbase)
__device__ u64 d_So[IMG_H * NW];   // new strong bits after hysteresis (rows 1..2046)
__device__ u64 d_bnd [BANDS * NW]; // speculative outgoing boundary of band k
__device__ u64 d_spec[BANDS * NW]; // speculative incoming boundary of band k
__device__ u64 d_trash[NW];        // discard sink for out-of-range stores
__device__ float d_pmax[256];      // per-block partial maxes

// ---------------- K1: max partial reduction (256 blocks, plain stores) ----------------
__global__ void k1_max(const float* __restrict__ img) {
    const float4* p4 = reinterpret_cast<const float4*>(img);
    const int n4 = (IMG_H * IMG_W) / 4;
    float m = 0.0f;
    for (int i = blockIdx.x * blockDim.x + threadIdx.x; i < n4;
         i += gridDim.x * blockDim.x) {
        float4 v = p4[i];
        m = fmaxf(m, fmaxf(fmaxf(v.x, v.y), fmaxf(v.z, v.w)));
    }
    for (int o = 16; o > 0; o >>= 1)
        m = fmaxf(m, __shfl_xor_sync(0xffffffffu, m, o));
    __shared__ float sm[8];
    int lane = threadIdx.x & 31, wid = threadIdx.x >> 5;
    if (lane == 0) sm[wid] = m;
    __syncthreads();
    if (wid == 0) {
        m = (lane < 8) ? sm[lane] : 0.0f;
        for (int o = 4; o > 0; o >>= 1)
            m = fmaxf(m, __shfl_xor_sync(0xffffffffu, m, o));
        if (lane == 0) d_pmax[blockIdx.x] = m;
    }
}

// ---------------- block-wide final max (blockDim == 256) ----------------
__device__ __forceinline__ float block_max256() {
    __shared__ float sm[8];
    __shared__ float smax;
    float v = d_pmax[threadIdx.x];
    for (int o = 16; o > 0; o >>= 1)
        v = fmaxf(v, __shfl_xor_sync(0xffffffffu, v, o));
    int lane = threadIdx.x & 31, wid = threadIdx.x >> 5;
    if (lane == 0) sm[wid] = v;
    __syncthreads();
    if (wid == 0) {
        float u = (lane < 8) ? sm[lane] : 0.0f;
        for (int o = 4; o > 0; o >>= 1)
            u = fmaxf(u, __shfl_xor_sync(0xffffffffu, u, o));
        if (lane == 0) smax = u;
    }
    __syncthreads();
    return smax;
}

// ---------------- K2: pack strong/weak bitmasks (1 warp per row) ----------------
__global__ void __launch_bounds__(256) k2_pack(const float* __restrict__ img) {
    float mx = block_max256();
    float high = mx * 0.15f;
    float low = high * 0.05f;

    int gw = (blockIdx.x * blockDim.x + threadIdx.x) >> 5;  // global warp = row
    int lane = threadIdx.x & 31;
    if (gw >= IMG_H) return;

    const float4* rp = reinterpret_cast<const float4*>(img + (size_t)gw * IMG_W) + lane * 16;
    u64 sb = 0, wb = 0;
#pragma unroll
    for (int k = 0; k < 16; ++k) {
        float4 v = rp[k];
        int b = k * 4;
        sb |= ((u64)(v.x > high)) << (b + 0);
        sb |= ((u64)(v.y > high)) << (b + 1);
        sb |= ((u64)(v.z > high)) << (b + 2);
        sb |= ((u64)(v.w > high)) << (b + 3);
        wb |= ((u64)((v.x >= low) && (v.x <= high))) << (b + 0);
        wb |= ((u64)((v.y >= low) && (v.y <= high))) << (b + 1);
        wb |= ((u64)((v.z >= low) && (v.z <= high))) << (b + 2);
        wb |= ((u64)((v.w >= low) && (v.w <= high))) << (b + 3);
    }
    d_S [gw * NW + lane] = sb;
    d_Wf[gw * NW + lane] = wb;
    if (lane == 0)  wb &= ~1ull;              // column 0 not interior
    if (lane == 31) wb &= ~(1ull << 63);      // column W-1 not interior
    d_W[gw * NW + lane] = wb;
}

// ---------------- K2b: A0 = S | (W & static_base), plain loads, no shuffles ----------------
__global__ void k2b_pre() {
    int gid = blockIdx.x * blockDim.x + threadIdx.x;
    int i = (gid >> 5) + 1;
    int l = gid & 31;
    if (i > IMG_H - 2) return;

    u64 cs  = d_S[i * NW + l];
    u64 ns  = d_S[(i + 1) * NW + l];
    u64 w   = d_W[i * NW + l];
    u64 csR = (l < 31) ? d_S[i * NW + l + 1] : 0;
    u64 nsL = (l > 0)  ? d_S[(i + 1) * NW + l - 1] : 0;
    u64 nsR = (l < 31) ? d_S[(i + 1) * NW + l + 1] : 0;

    u64 SB = ((cs >> 1) | (csR << 63)) | ((ns << 1) | (nsL >> 63)) | ns |
             ((ns >> 1) | (nsR << 63));
    d_A0[i * NW + l] = cs | (w & SB);
}

// ---------------- hysteresis core ----------------
__device__ __forceinline__ u64 dil(u64 s, int l) {
    const unsigned F = 0xffffffffu;
    u64 sl = __shfl_up_sync(F, s, 1);   sl = (l == 0)  ? 0 : sl;
    u64 sr = __shfl_down_sync(F, s, 1); sr = (l == 31) ? 0 : sr;
    return s | ((s << 1) | (sl >> 63)) | ((s >> 1) | (sr << 63));
}

// One row of the recurrence. Updates nb (dilated new-strong) for the next row.
__device__ __forceinline__ u64 row_step(u64 a0, u64 w, u64& nb, int l) {
    const unsigned F = 0xffffffffu;
    u64 a = a0 | (w & nb);
    u64 p = w & ~a;
    u64 x = a | w;

    unsigned lo = (unsigned)(a & 1ull) | (((unsigned)(p & 1ull)) << 1);
    unsigned loR = __shfl_down_sync(F, lo, 1);
    loR = (l == 31) ? 0u : loR;

    u64 t1 = x + a;                      // in-word carry chain, cin=0
    unsigned Gm = __ballot_sync(F, t1 < x);
    unsigned Pm = __ballot_sync(F, p == ~0ull);

    unsigned x32 = Gm | Pm;
    unsigned cv32 = (x32 + Gm) ^ (x32 ^ Gm);   // bit l = carry into lane l
    u64 cin = (u64)((cv32 >> l) & 1u);

    u64 t2 = t1 + cin;
    u64 cv = t2 ^ x ^ a;                        // bit j = carry into bit j
    u64 co = (u64)(t1 < x) | (cin & (u64)(t1 == ~0ull));
    u64 s = (cv >> 1) | (co << 63);             // new-strong bits of this row

    unsigned cinR = ((cv32 >> l) >> 1) & 1u;
    u64 rb = (u64)((loR & 1u) | ((loR >> 1) & cinR));
    nb = s | ((s << 1) | cin) | ((s >> 1) | (rb << 63));
    return s;
}

// Fully-unrolled band runner. TRIPS iterations from row ws; rows with
// cnt >= WARMN are stored (tail-band overflow redirected to d_trash via SEL).
template<int TRIPS, int WARMN>
__device__ __forceinline__ void run_band(int ws, u64 nb, int l,
                                         u64* specp, u64* outp) {
    u64 A0r[PFD], Wr[PFD];
#pragma unroll
    for (int d = 0; d < PFD; ++d) {
        int r = ws + d; r = (r > IMG_H - 2) ? (IMG_H - 2) : r;
        A0r[d] = d_A0[r * NW + l];
        Wr[d]  = d_W [r * NW + l];
    }
    u64 spec = 0, last = 0;
#pragma unroll
    for (int cnt = 0; cnt < TRIPS; ++cnt) {
        int i = ws + cnt;
        u64 a0 = A0r[cnt & (PFD - 1)];
        u64 w  = Wr [cnt & (PFD - 1)];
        int pr = i + PFD; pr = (pr > IMG_H - 2) ? (IMG_H - 2) : pr;
        A0r[cnt & (PFD - 1)] = d_A0[pr * NW + l];
        Wr [cnt & (PFD - 1)] = d_W [pr * NW + l];

        u64 s = row_step(a0, w, nb, l);
        if (cnt >= WARMN) {
            u64* p = (i <= IMG_H - 2) ? &d_So[i * NW + l] : &d_trash[l];
            *p = s;
        }
        if (WARMN > 0 && cnt == WARMN - 1) spec = s;
        last = s;
    }
    if (specp) *specp = spec;
    *outp = last;
}

// Generic runtime-bound runner (fixup path only).
__device__ u64 run_rows_generic(int rs, int re, u64 nb, int l) {
    u64 last = 0;
    for (int i = rs; i < re; ++i) {
        u64 a0 = d_A0[i * NW + l];
        u64 w  = d_W [i * NW + l];
        u64 s = row_step(a0, w, nb, l);
        d_So[i * NW + l] = s;
        last = s;
    }
    return last;
}

// ---------------- K3a: band-parallel speculative hysteresis ----------------
__global__ void __launch_bounds__(32, 1) k3a_spec() {
    const int l = threadIdx.x;
    const int k = blockIdx.x;
    if (k == 0) {
        u64 s0 = d_S[0 * NW + l];
        u64 out;
        run_band<OWN, 0>(1, dil(s0, l), l, nullptr, &out);
        d_bnd[l] = out;
    } else {
        int rs = 1 + OWN * k;
        int ws = rs - WARM;
        u64 seed = d_S[(ws - 1) * NW + l];
        u64 spec, out;
        run_band<OWN + WARM, WARM>(ws, dil(seed, l), l, &spec, &out);
        d_spec[k * NW + l] = spec;
        d_bnd[k * NW + l] = out;
    }
}

// ---------------- K3b: verify; sequential in-block fixup if needed ----------------
__global__ void __launch_bounds__(1024, 1) k3b_fix() {
    const unsigned F = 0xffffffffu;
    const int tid = threadIdx.x;

    bool m = true;
    for (int wdx = tid; wdx < (BANDS - 1) * 32; wdx += 1024) {
        int band = (wdx >> 5) + 1, lane = wdx & 31;
        m &= (d_spec[band * NW + lane] == d_bnd[(band - 1) * NW + lane]);
    }
    if (__syncthreads_and(m)) return;   // expected case: all speculation exact

    // Sequential fixup: exactness preserved — if the true incoming boundary
    // equals the speculated one, the band's stored rows are already correct;
    // otherwise recompute from truth.
    __shared__ u64 tout[BANDS * 32];
    const int l = tid & 31, wid = tid >> 5;
    for (int step = 0; step < BANDS; ++step) {
        if ((step & 31) == wid) {
            if (step == 0) {
                tout[l] = d_bnd[l];
            } else {
                int rs = 1 + OWN * step;
                int re = rs + OWN; if (re > IMG_H - 1) re = IMG_H - 1;
                u64 tin = tout[(step - 1) * 32 + l];
                u64 spec = d_spec[step * NW + l];
                if (__ballot_sync(F, tin == spec) == F) {
                    tout[step * 32 + l] = d_bnd[step * NW + l];
                } else {
                    tout[step * 32 + l] = run_rows_generic(rs, re, dil(tin, l), l);
                }
            }
        }
        __syncthreads();
    }
}

// ---------------- K4: reconstruct float output from bitmasks only ----------------
__global__ void k4_out(float* __restrict__ out) {
    int idx = blockIdx.x * blockDim.x + threadIdx.x;   // one float4 per thread
    const int n4 = (IMG_H * IMG_W) / 4;
    if (idx >= n4) return;
    int row = idx >> 9;          // 512 float4 per row
    int c = (idx & 511) * 4;
    int wi = row * NW + (c >> 6);
    int sh = c & 63;

    u64 sb = d_S [wi] >> sh;
    u64 fb = d_Wf[wi] >> sh;

    float4 o;
    if (row == 0 || row == IMG_H - 1) {
#pragma unroll
        for (int j = 0; j < 4; ++j)
            (&o.x)[j] = ((sb >> j) & 1ull) ? 255.0f : (((fb >> j) & 1ull) ? 25.0f : 0.0f);
    } else {
        u64 wb = d_W [wi] >> sh;
        u64 ob = d_So[wi] >> sh;
#pragma unroll
        for (int j = 0; j < 4; ++j) {
            float r;
            if ((wb >> j) & 1ull)      r = ((ob >> j) & 1ull) ? 255.0f : 0.0f;
            else if ((sb >> j) & 1ull) r = 255.0f;
            else                       r = ((fb >> j) & 1ull) ? 25.0f : 0.0f;
            (&o.x)[j] = r;
        }
    }
    reinterpret_cast<float4*>(out)[idx] = o;
}

extern "C" void kernel_launch(void* const* d_in, const int* in_sizes, int n_in,
                              void* d_out, int out_size) {
    const float* img = (const float*)d_in[0];
    float* out = (float*)d_out;
    (void)in_sizes; (void)n_in; (void)out_size;

    k1_max<<<256, 256>>>(img);
    k2_pack<<<IMG_H / 8, 256>>>(img);              // 1 warp per row
    k2b_pre<<<((IMG_H - 2) * 32 + 255) / 256, 256>>>();
    k3a_spec<<<BANDS, 32>>>();
    k3b_fix<<<1, 1024>>>();
    k4_out<<<(IMG_H * IMG_W / 4 + 255) / 256, 256>>>(out);
}